// round 13
// baseline (speedup 1.0000x reference)
#include <cuda_runtime.h>

// CTC loss forward, single fused kernel, producer/consumer within each block.
// 64 blocks (one per batch), 9 warps. Warps 1-8 gather+exp emissions into
// smem sm[t][0..31]=exp(lp[t,b,c1(l)]), sm[t][32]=exp(lp[t,b,blank]), rows
// striped t%8, in 8 double-buffered groups of 4 rows: group g+1's LDGs are
// issued BEFORE group g's exp+STS so miss latency overlaps the store phase.
// bar g+1 after group g guarantees rows <= 32g+31; extra bar 9 after all
// groups serves the consumer's tail (avoids double-sync deadlock on bar 8).
// Warp 0: linear-domain fused-pair recursion off LDS; lane l owns states 2l
// ("e"), 2l+1 ("o"); lane 31 also state 64 ("a2"). Consumer segment s
// (8 quads; prefetch rows <= 32s+36) waits bar s+2. Exact pow2 rescale every
// 4 steps (redux.sync.max.s32 on float bits), lag-applied.

constexpr int B_SZ  = 64;
constexpr int C_SZ  = 8000;
constexpr int L_MAX = 32;
constexpr int ROW   = 33;
constexpr int NTHR  = 288;               // 1 consumer + 8 producer warps

__device__ float g_loss[B_SZ];
__device__ int   g_count;

__device__ __forceinline__ int warp_max_s32(int v) {
    int r;
    asm volatile("redux.sync.max.s32 %0, %1, 0xffffffff;" : "=r"(r) : "r"(v));
    return r;
}
__device__ __forceinline__ float shup(float v, int d) {
    return __shfl_up_sync(0xffffffffu, v, d);
}

struct QB { float p1[4], pb[4], pmA, pmB; };

__device__ __forceinline__ void loadq(const float* __restrict__ sm, int q,
                                      int l, float m0, QB& d) {
    const int r0 = 4 * q + 1;            // rows r0..r0+3; pad row covers 256
#pragma unroll
    for (int j = 0; j < 4; j++) {
        d.p1[j] = sm[(r0 + j) * ROW + l];
        d.pb[j] = sm[(r0 + j) * ROW + 32];
    }
    // l==0 reads [r*ROW-1] = previous row's blank slot; masked by m0
    d.pmA = sm[r0 * ROW + l - 1] * m0;
    d.pmB = sm[(r0 + 2) * ROW + l - 1] * m0;
}

__device__ __forceinline__ void do_quad(float& e, float& o, float& a2,
                                        const QB& c, float skf, float skfm,
                                        float m0, float m1) {
#pragma unroll
    for (int h = 0; h < 2; h++) {        // two fused pairs = 4 steps
        const float pm  = h ? c.pmB : c.pmA;
        const float p1a = c.p1[2 * h],     pba = c.pb[2 * h];
        const float p1b = c.p1[2 * h + 1], pbb = c.pb[2 * h + 1];
        const float x1  = shup(o, 1) * m0;
        const float x2  = shup(o, 2) * m1;
        const float y1  = shup(e, 1);
        const float otm = ((x1 + y1) + skfm * x2) * pm;
        const float et  = (e + x1) * pba;
        const float ot  = ((o + e) + skf * x1) * p1a;
        const float at  = (a2 + o) * pba;
        e  = (et + otm) * pbb;
        o  = ((ot + et) + skf * otm) * p1b;
        a2 = (at + ot) * pbb;
    }
}

__device__ __forceinline__ void rescale(float& e, float& o, float& a2,
                                        int& g, float& fpend, int& fexp) {
    e *= fpend; o *= fpend; a2 *= fpend; g += fexp;
    const int mi = warp_max_s32(__float_as_int(fmaxf(e, fmaxf(o, a2))));
    int fx = 207 - ((mi >> 23) & 0xff);              // 80 - E, exact pow2
    fx = fx > 127 ? 127 : (fx < -126 ? -126 : fx);
    fpend = __int_as_float((fx + 127) << 23);
    fexp  = fx;
}

__global__ void __launch_bounds__(NTHR, 1)
ctc_kernel(const float* __restrict__ lp,
           const int*   __restrict__ targets,
           const int*   __restrict__ in_len,
           const int*   __restrict__ tgt_len,
           float*       __restrict__ out) {
    __shared__ float sm[257 * ROW];                 // 256 rows + 1 pad row
    const int b   = blockIdx.x;
    const int tid = threadIdx.x;
    const int l   = tid & 31;
    const int w   = tid >> 5;
    const size_t BC = (size_t)B_SZ * C_SZ;

    const int tl   = tgt_len[b];
    const int last = in_len[b] - 1;                 // in [128, 255]
    const int c1   = (l < tl) ? targets[b * L_MAX + l] : 0;

    if (w > 0) {
        // ---- producer warp pw: rows t = pw + 8k, k = 0..31, 8 groups of 4 ----
        const int pw = w - 1;
        const float* pbp = lp + (size_t)pw * BC + (size_t)b * C_SZ;
        const float* p1p = pbp + c1;
        float* srow = sm + pw * ROW;

        float v1[2][4], vb[2][4];
#pragma unroll
        for (int j = 0; j < 4; j++) {               // prologue: load group 0
            const size_t off = (size_t)j * 8 * BC;
            v1[0][j] = __ldg(p1p + off);
            vb[0][j] = __ldg(pbp + off);
        }
#pragma unroll
        for (int g = 0; g < 8; g++) {
            if (g < 7) {                            // issue group g+1 loads first
#pragma unroll
                for (int j = 0; j < 4; j++) {
                    const size_t off = (size_t)(4 * (g + 1) + j) * 8 * BC;
                    v1[(g + 1) & 1][j] = __ldg(p1p + off);
                    vb[(g + 1) & 1][j] = __ldg(pbp + off);
                }
            }
#pragma unroll
            for (int j = 0; j < 4; j++) {           // store group g
                const int k = 4 * g + j;
                srow[k * 8 * ROW + l] = __expf(v1[g & 1][j]);
                if (l == 0) srow[k * 8 * ROW + 32] = __expf(vb[g & 1][j]);
            }
            asm volatile("bar.arrive %0, 288;" :: "r"(g + 1) : "memory");
        }
        asm volatile("bar.arrive 9, 288;" ::: "memory");   // tail barrier
        return;
    }

    // ---- consumer warp ----
    const int  c1p  = __shfl_up_sync(0xffffffffu, c1, 1);
    const bool skip = (c1 != 0) && ((l == 0) || (c1 != c1p));
    const float skf  = skip ? 1.f : 0.f;
    const float skfm = shup(skf, 1);
    const float m0   = (l == 0) ? 0.f : 1.f;
    const float m1   = (l <= 1) ? 0.f : 1.f;

    asm volatile("bar.sync 1, 288;" ::: "memory");  // rows <= 31 available

    // t=0 init (prob domain, pre-scaled 2^80)
    float e = 0.f, o = 0.f, a2 = 0.f;
    if (l == 0) {
        e = sm[32] * 0x1p80f;
        o = (tl > 0) ? sm[0] * 0x1p80f : 0.f;
    }
    int g = 80;
    float fpend = 1.f;
    int   fexp  = 0;

    const int nq  = last >> 2;                      // in [32, 63]
    const int rem = last & 3;

    QB A, Bq;
    loadq(sm, 0, l, m0, A);

    int q = 0;
#pragma unroll 1
    for (int s = 0; s < 7; s++) {                   // 8-quad segments
        if (q + 1 >= nq) break;                     // only leftover/epilogue left
        asm volatile("bar.sync %0, 288;" :: "r"(s + 2) : "memory");
        const int qend = min(nq, 8 * (s + 1));
        while (q + 1 < qend) {                      // quads in ping/pong pairs
            rescale(e, o, a2, g, fpend, fexp);      // every 4 steps, lagged
            loadq(sm, q + 1, l, m0, Bq);
            do_quad(e, o, a2, A, skf, skfm, m0, m1);  q++;
            rescale(e, o, a2, g, fpend, fexp);
            loadq(sm, q + 1, l, m0, A);
            do_quad(e, o, a2, Bq, skf, skfm, m0, m1); q++;
        }
    }
    if (q < nq) {                                   // tail: all rows ready
        asm volatile("bar.sync 9, 288;" ::: "memory");
        while (q + 1 < nq) {
            rescale(e, o, a2, g, fpend, fexp);
            loadq(sm, q + 1, l, m0, Bq);
            do_quad(e, o, a2, A, skf, skfm, m0, m1);  q++;
            rescale(e, o, a2, g, fpend, fexp);
            loadq(sm, q + 1, l, m0, A);
            do_quad(e, o, a2, Bq, skf, skfm, m0, m1); q++;
        }
        if (q < nq) {                               // leftover quad (nq odd)
            rescale(e, o, a2, g, fpend, fexp);
            loadq(sm, q + 1, l, m0, Bq);
            do_quad(e, o, a2, A, skf, skfm, m0, m1); q++;
        }
    }

    // epilogue: rem steps; quad-nq data sits in A (nq even) or Bq (nq odd)
    float ep1[3], epb[3];
#pragma unroll
    for (int j = 0; j < 3; j++) {
        ep1[j] = (nq & 1) ? Bq.p1[j] : A.p1[j];
        epb[j] = (nq & 1) ? Bq.pb[j] : A.pb[j];
    }
#pragma unroll
    for (int j = 0; j < 3; j++) {
        if (j < rem) {
            const float x1 = shup(o, 1) * m0;
            const float en = (e + x1) * epb[j];
            const float on = ((o + e) + skf * x1) * ep1[j];
            const float an = (a2 + o) * epb[j];
            e = en; o = on; a2 = an;
        }
    }

    // final states: i_blank = 2*tl (e @ lane tl, or a2 @ lane31 if tl==32),
    //               i_char  = 2*tl-1 (o @ lane tl-1)
    const float vbl = __shfl_sync(0xffffffffu, e, tl & 31);
    const float vbh = __shfl_sync(0xffffffffu, a2, 31);
    const float vb  = (tl >= 32) ? vbh : vbl;
    const int   icl = (tl > 0) ? (tl - 1) : 0;
    const float vc  = __shfl_sync(0xffffffffu, o, icl);
    const float tot = (tl > 0) ? (vb + vc) : vb;

    if (l == 0) {
        const float total_log = logf(tot) - (float)g * 0.69314718055994531f;
        const int   denom     = (tl > 0) ? tl : 1;
        g_loss[b] = -total_log / (float)denom;
        __threadfence();
        const int old = atomicAdd(&g_count, 1);
        if (old == B_SZ - 1) {
            g_count = 0;                            // reset for next graph replay
            __threadfence();
            float s = 0.f;
            for (int i = 0; i < B_SZ; i++) s += __ldcg((const float*)&g_loss[i]);
            out[0] = s / (float)B_SZ;
        }
    }
}

extern "C" void kernel_launch(void* const* d_in, const int* in_sizes, int n_in,
                              void* d_out, int out_size) {
    const float* log_probs  = (const float*)d_in[0];
    const int*   targets    = (const int*)d_in[1];
    const int*   input_len  = (const int*)d_in[2];
    const int*   target_len = (const int*)d_in[3];
    float* out = (float*)d_out;
    (void)in_sizes; (void)n_in; (void)out_size;

    ctc_kernel<<<B_SZ, NTHR>>>(log_probs, targets, input_len, target_len, out);
}

// round 14
// speedup vs baseline: 1.0173x; 1.0173x over previous
#include <cuda_runtime.h>

// CTC loss forward, one kernel, 128 blocks in a single wave.
// Block b (<64): scan block for batch b. 9 warps: warp 0 = consumer (linear-
//   domain fused-pair CTC recursion off LDS, exact pow2 rescale every 4 steps
//   via redux.sync.max.s32, lag-applied). Warps 1-8 = producers: gather+exp
//   rows 0..127 directly from log_probs (striped t%8, 4 groups of 4 rows,
//   bars 1..4 guarantee rows <=31/63/95/127), then copy rows 128..255 from
//   g_em (written by the helper block) in 4 segments (bars 5..8 guarantee
//   rows <=159/191/223/255), bar 9 = done.
// Block 64+b: helper. 8 gather warps fill g_em[b][t-128][0..32] =
//   exp(lp[t,b,c1/blank]) for t=128..255 in 4 x 32-row segments, publishing
//   each via __threadfence + flag. Flags are reset by the scan consumer after
//   bar 9 (producers provably past their polls) -> deterministic replays.

constexpr int B_SZ  = 64;
constexpr int C_SZ  = 8000;
constexpr int L_MAX = 32;
constexpr int ROW   = 33;
constexpr int NTHR  = 288;

__device__ float g_em[B_SZ][128][ROW];   // helper-gathered rows 128..255
__device__ int   g_flag[B_SZ][4];
__device__ float g_loss[B_SZ];
__device__ int   g_count;

__device__ __forceinline__ int warp_max_s32(int v) {
    int r;
    asm volatile("redux.sync.max.s32 %0, %1, 0xffffffff;" : "=r"(r) : "r"(v));
    return r;
}
__device__ __forceinline__ float shup(float v, int d) {
    return __shfl_up_sync(0xffffffffu, v, d);
}

struct QB { float p1[4], pb[4], pmA, pmB; };

__device__ __forceinline__ void loadq(const float* __restrict__ sm, int q,
                                      int l, float m0, QB& d) {
    const int r0 = 4 * q + 1;            // rows r0..r0+3; pad row covers 256
#pragma unroll
    for (int j = 0; j < 4; j++) {
        d.p1[j] = sm[(r0 + j) * ROW + l];
        d.pb[j] = sm[(r0 + j) * ROW + 32];
    }
    // l==0 reads [r*ROW-1] = previous row's blank slot; masked by m0
    d.pmA = sm[r0 * ROW + l - 1] * m0;
    d.pmB = sm[(r0 + 2) * ROW + l - 1] * m0;
}

__device__ __forceinline__ void do_quad(float& e, float& o, float& a2,
                                        const QB& c, float skf, float skfm,
                                        float m0, float m1) {
#pragma unroll
    for (int h = 0; h < 2; h++) {        // two fused pairs = 4 steps
        const float pm  = h ? c.pmB : c.pmA;
        const float p1a = c.p1[2 * h],     pba = c.pb[2 * h];
        const float p1b = c.p1[2 * h + 1], pbb = c.pb[2 * h + 1];
        const float x1  = shup(o, 1) * m0;
        const float x2  = shup(o, 2) * m1;
        const float y1  = shup(e, 1);
        const float otm = ((x1 + y1) + skfm * x2) * pm;
        const float et  = (e + x1) * pba;
        const float ot  = ((o + e) + skf * x1) * p1a;
        const float at  = (a2 + o) * pba;
        e  = (et + otm) * pbb;
        o  = ((ot + et) + skf * otm) * p1b;
        a2 = (at + ot) * pbb;
    }
}

__device__ __forceinline__ void rescale(float& e, float& o, float& a2,
                                        int& g, float& fpend, int& fexp) {
    e *= fpend; o *= fpend; a2 *= fpend; g += fexp;
    const int mi = warp_max_s32(__float_as_int(fmaxf(e, fmaxf(o, a2))));
    int fx = 207 - ((mi >> 23) & 0xff);              // 80 - E, exact pow2
    fx = fx > 127 ? 127 : (fx < -126 ? -126 : fx);
    fpend = __int_as_float((fx + 127) << 23);
    fexp  = fx;
}

__global__ void __launch_bounds__(NTHR, 1)
ctc_kernel(const float* __restrict__ lp,
           const int*   __restrict__ targets,
           const int*   __restrict__ in_len,
           const int*   __restrict__ tgt_len,
           float*       __restrict__ out) {
    __shared__ float sm[257 * ROW];                 // 256 rows + 1 pad row
    const int tid = threadIdx.x;
    const int l   = tid & 31;
    const int w   = tid >> 5;
    const size_t BC = (size_t)B_SZ * C_SZ;

    // ---------------- helper blocks: gather rows 128..255 into g_em ----------
    if (blockIdx.x >= B_SZ) {
        const int b  = blockIdx.x - B_SZ;
        const int tl = tgt_len[b];
        const int c1 = (l < tl) ? targets[b * L_MAX + l] : 0;
        const float* pbp = lp + (size_t)128 * BC + (size_t)b * C_SZ;
        const float* p1p = pbp + c1;

#pragma unroll
        for (int s = 0; s < 4; s++) {               // segment s: rows 128+32s..159+32s
            if (w < 8) {
                float v1[4], vb[4];
#pragma unroll
                for (int j = 0; j < 4; j++) {       // row offset within 128..255
                    const int k = w + 8 * (4 * s + j);
                    v1[j] = __ldg(p1p + (size_t)k * BC);
                    vb[j] = __ldg(pbp + (size_t)k * BC);
                }
#pragma unroll
                for (int j = 0; j < 4; j++) {
                    const int k = w + 8 * (4 * s + j);
                    float* d = &g_em[b][k][0];
                    d[l] = __expf(v1[j]);
                    if (l == 0) d[32] = __expf(vb[j]);
                }
                __threadfence();
            }
            __syncthreads();
            if (tid == 0) *(volatile int*)&g_flag[b][s] = 1;
        }
        return;
    }

    // ---------------- scan blocks ----------------
    const int b    = blockIdx.x;
    const int tl   = tgt_len[b];
    const int last = in_len[b] - 1;                 // in [128, 255]
    const int c1   = (l < tl) ? targets[b * L_MAX + l] : 0;

    if (w > 0) {
        // ---- producer warp pw: gather rows 0..127 (t = pw + 8k, k=0..15) ----
        const int pw = w - 1;
        const float* pbp = lp + (size_t)pw * BC + (size_t)b * C_SZ;
        const float* p1p = pbp + c1;
        float* srow = sm + pw * ROW;

#pragma unroll
        for (int g = 0; g < 4; g++) {               // bar g+1: rows <= 32g+31
            float v1[4], vb[4];
#pragma unroll
            for (int j = 0; j < 4; j++) {
                const size_t off = (size_t)(4 * g + j) * 8 * BC;
                v1[j] = __ldg(p1p + off);
                vb[j] = __ldg(pbp + off);
            }
#pragma unroll
            for (int j = 0; j < 4; j++) {
                const int k = 4 * g + j;
                srow[k * 8 * ROW + l] = __expf(v1[j]);
                if (l == 0) srow[k * 8 * ROW + 32] = __expf(vb[j]);
            }
            asm volatile("bar.arrive %0, 288;" :: "r"(g + 1) : "memory");
        }
        // ---- copy rows 128..255 from g_em (bars 5..8) ----
#pragma unroll
        for (int s = 0; s < 4; s++) {
            while (*(volatile int*)&g_flag[b][s] == 0) { }
            __threadfence();                        // acquire
#pragma unroll
            for (int j = 0; j < 4; j++) {
                const int k = 32 * s + pw * 4 + j;  // local row in g_em
                const int r = 128 + k;
                sm[r * ROW + l] = __ldcg(&g_em[b][k][l]);
                if (l == 0) sm[r * ROW + 32] = __ldcg(&g_em[b][k][32]);
            }
            asm volatile("bar.arrive %0, 288;" :: "r"(s + 5) : "memory");
        }
        asm volatile("bar.arrive 9, 288;" ::: "memory");
        return;
    }

    // ---- consumer warp ----
    const int  c1p  = __shfl_up_sync(0xffffffffu, c1, 1);
    const bool skip = (c1 != 0) && ((l == 0) || (c1 != c1p));
    const float skf  = skip ? 1.f : 0.f;
    const float skfm = shup(skf, 1);
    const float m0   = (l == 0) ? 0.f : 1.f;
    const float m1   = (l <= 1) ? 0.f : 1.f;

    asm volatile("bar.sync 1, 288;" ::: "memory");  // rows <= 31 available

    // t=0 init (prob domain, pre-scaled 2^80)
    float e = 0.f, o = 0.f, a2 = 0.f;
    if (l == 0) {
        e = sm[32] * 0x1p80f;
        o = (tl > 0) ? sm[0] * 0x1p80f : 0.f;
    }
    int g = 80;
    float fpend = 1.f;
    int   fexp  = 0;

    const int nq  = last >> 2;                      // in [32, 63]
    const int rem = last & 3;

    QB A, Bq;
    loadq(sm, 0, l, m0, A);

    int q = 0;
#pragma unroll 1
    for (int s = 0; s < 7; s++) {                   // 8-quad segments
        if (q + 1 >= nq) break;
        asm volatile("bar.sync %0, 288;" :: "r"(s + 2) : "memory");
        const int qend = min(nq, 8 * (s + 1));
        while (q + 1 < qend) {                      // quads in ping/pong pairs
            rescale(e, o, a2, g, fpend, fexp);      // every 4 steps, lagged
            loadq(sm, q + 1, l, m0, Bq);
            do_quad(e, o, a2, A, skf, skfm, m0, m1);  q++;
            rescale(e, o, a2, g, fpend, fexp);
            loadq(sm, q + 1, l, m0, A);
            do_quad(e, o, a2, Bq, skf, skfm, m0, m1); q++;
        }
    }
    // all rows ready + producers past their flag polls (needed before reset)
    asm volatile("bar.sync 9, 288;" ::: "memory");
    while (q + 1 < nq) {
        rescale(e, o, a2, g, fpend, fexp);
        loadq(sm, q + 1, l, m0, Bq);
        do_quad(e, o, a2, A, skf, skfm, m0, m1);  q++;
        rescale(e, o, a2, g, fpend, fexp);
        loadq(sm, q + 1, l, m0, A);
        do_quad(e, o, a2, Bq, skf, skfm, m0, m1); q++;
    }
    if (q < nq) {                                   // leftover quad (nq odd)
        rescale(e, o, a2, g, fpend, fexp);
        loadq(sm, q + 1, l, m0, Bq);
        do_quad(e, o, a2, A, skf, skfm, m0, m1);  q++;
    }

    // epilogue: rem steps; quad-nq data sits in A (nq even) or Bq (nq odd)
    float ep1[3], epb[3];
#pragma unroll
    for (int j = 0; j < 3; j++) {
        ep1[j] = (nq & 1) ? Bq.p1[j] : A.p1[j];
        epb[j] = (nq & 1) ? Bq.pb[j] : A.pb[j];
    }
#pragma unroll
    for (int j = 0; j < 3; j++) {
        if (j < rem) {
            const float x1 = shup(o, 1) * m0;
            const float en = (e + x1) * epb[j];
            const float on = ((o + e) + skf * x1) * ep1[j];
            const float an = (a2 + o) * epb[j];
            e = en; o = on; a2 = an;
        }
    }

    // final states: i_blank = 2*tl (e @ lane tl, or a2 @ lane31 if tl==32),
    //               i_char  = 2*tl-1 (o @ lane tl-1)
    const float vbl = __shfl_sync(0xffffffffu, e, tl & 31);
    const float vbh = __shfl_sync(0xffffffffu, a2, 31);
    const float vb  = (tl >= 32) ? vbh : vbl;
    const int   icl = (tl > 0) ? (tl - 1) : 0;
    const float vc  = __shfl_sync(0xffffffffu, o, icl);
    const float tot = (tl > 0) ? (vb + vc) : vb;

    if (l == 0) {
        // reset flags for the next graph replay (producers are past bar 9)
#pragma unroll
        for (int s = 0; s < 4; s++) *(volatile int*)&g_flag[b][s] = 0;

        const float total_log = logf(tot) - (float)g * 0.69314718055994531f;
        const int   denom     = (tl > 0) ? tl : 1;
        g_loss[b] = -total_log / (float)denom;
        __threadfence();
        const int old = atomicAdd(&g_count, 1);
        if (old == B_SZ - 1) {
            g_count = 0;                            // reset for next graph replay
            __threadfence();
            float s = 0.f;
            for (int i = 0; i < B_SZ; i++) s += __ldcg((const float*)&g_loss[i]);
            out[0] = s / (float)B_SZ;
        }
    }
}

extern "C" void kernel_launch(void* const* d_in, const int* in_sizes, int n_in,
                              void* d_out, int out_size) {
    const float* log_probs  = (const float*)d_in[0];
    const int*   targets    = (const int*)d_in[1];
    const int*   input_len  = (const int*)d_in[2];
    const int*   target_len = (const int*)d_in[3];
    float* out = (float*)d_out;
    (void)in_sizes; (void)n_in; (void)out_size;

    ctc_kernel<<<2 * B_SZ, NTHR>>>(log_probs, targets, input_len, target_len, out);
}